// round 8
// baseline (speedup 1.0000x reference)
#include <cuda_runtime.h>
#include <cooperative_groups.h>
#include <cstdint>

namespace cg = cooperative_groups;

// NLCCSCriterion — 128 independent 256x256 masks.
// R7: 2-CTA cluster per image; each CTA owns half the label array in its smem
// (~73KB/CTA => 2 CTAs resident per SM => 64 warps). Union-find spans halves
// via DSMEM (base-pointer select on label bit 15). Phase logic = R3 (best).

#define HH 256
#define WW 256
#define NPIX (HH * WW)          // 65536
#define NIMG 128
#define NT 1024
#define HALFPIX (NPIX / 2)      // 32768 pixels per CTA
#define PPT (HALFPIX / NT)      // 32
#define NWORDS (NPIX / 32)      // 2048 (full image bitmap, mirrored in both CTAs)
#define LWORDS (NWORDS / 2)     // 1024 words owned per CTA
#define BGLAB 0x10000u          // sentinel label S = 65536

// per-CTA smem offsets (bytes)
#define OFF_L     0             // uint16 L[32768] (this CTA's half)  : 65536
#define OFF_FGW   65536         // uint32 fgw[2048] (FULL image)      : 8192
#define OFF_TOP   73728         // u64 warp top2[64]                  : 512
#define OFF_WSF   74240         // float warp sums[32]                : 128
#define OFF_WSI   74368         // int warp sums[32]                  : 128
#define OFF_BB    74496         // int bbox[8] (0..3 local, 4..7 comb): 32
#define OFF_MISC  74528         // int misc[4]: [0]=second/flag [1]=fgtot_local
#define OFF_X     74544         // u64 xk1, u64 xk2, float xsum       : 24
#define SMEM_BYTES 74576

__device__ int      g_area[NIMG][NPIX];   // all-zero between calls (owner rezeros)
__device__ float    g_loss[NIMG];
__device__ unsigned g_count;

// select local/peer half base by label bit 15
__device__ __forceinline__ unsigned short* lp(unsigned short* b0, unsigned short* b1, unsigned p) {
    unsigned short* base = (p & 0x8000u) ? b1 : b0;
    return base + (p & 0x7FFFu);
}

// 16-bit atomicMin built on 32-bit CAS (valid on local smem and DSMEM)
__device__ __forceinline__ unsigned short atomMinU16(unsigned short* a, unsigned short v) {
    unsigned* w = (unsigned*)((uintptr_t)a & ~(uintptr_t)3);
    int sh = ((uintptr_t)a & 2) ? 16 : 0;
    unsigned old = *w;
    while (true) {
        unsigned short cur = (unsigned short)(old >> sh);
        if (cur <= v) return cur;
        unsigned nw = (old & ~(0xFFFFu << sh)) | ((unsigned)v << sh);
        unsigned prev = atomicCAS(w, old, nw);
        if (prev == old) return cur;                 // value seen before our write
        old = prev;
    }
}

// path-halving find across the split label array
__device__ __forceinline__ unsigned find_halve(unsigned short* b0, unsigned short* b1, unsigned a) {
    unsigned short n;
    while ((n = *lp(b0, b1, a)) != (unsigned short)a) {
        unsigned short nn = *lp(b0, b1, n);
        *lp(b0, b1, a) = nn;
        a = nn;
    }
    return a;
}

__device__ __forceinline__ void merge_labels(unsigned short* b0, unsigned short* b1,
                                             unsigned a, unsigned b) {
    while (true) {
        a = find_halve(b0, b1, a);
        b = find_halve(b0, b1, b);
        if (a == b) return;
        unsigned hi = a > b ? a : b;
        unsigned lo = a + b - hi;
        unsigned short old = atomMinU16(lp(b0, b1, hi), (unsigned short)lo);
        if (old == (unsigned short)hi) return;       // linked hi -> lo
        a = old;
        b = lo;
    }
}

__device__ __forceinline__ void top2_merge(unsigned long long& k1, unsigned long long& k2,
                                           unsigned long long o1, unsigned long long o2) {
    if (o1 > k1) { k2 = (k1 > o2) ? k1 : o2; k1 = o1; }
    else if (o1 > k2) k2 = o1;
}

__global__ __launch_bounds__(NT, 2) __cluster_dims__(2, 1, 1)
void nlccs_kernel(const float* __restrict__ in, float* __restrict__ out) {
    extern __shared__ unsigned char sraw[];
    unsigned short*      Lloc   = (unsigned short*)(sraw + OFF_L);
    unsigned int*        fgw    = (unsigned int*)(sraw + OFF_FGW);
    unsigned long long*  s_top  = (unsigned long long*)(sraw + OFF_TOP);
    float*               s_wsf  = (float*)(sraw + OFF_WSF);
    int*                 s_wsi  = (int*)(sraw + OFF_WSI);
    int*                 s_bb   = (int*)(sraw + OFF_BB);
    int*                 s_misc = (int*)(sraw + OFF_MISC);
    unsigned long long*  s_xk   = (unsigned long long*)(sraw + OFF_X);
    float*               s_xs   = (float*)(sraw + OFF_X + 16);

    cg::cluster_group cluster = cg::this_cluster();
    const unsigned rank  = cluster.block_rank();       // 0 or 1 (== blockIdx.x & 1)
    const unsigned prank = rank ^ 1u;
    const int t    = threadIdx.x;
    const int lane = t & 31;
    const int warp = t >> 5;
    const int img_idx  = blockIdx.x >> 1;
    const unsigned pixbase  = rank << 15;              // global index of local pixel 0
    const unsigned wordbase = rank << 10;              // global index of local word 0
    const float* img  = in + (size_t)img_idx * NPIX;
    int*         area = &g_area[img_idx][0];

    // peer pointers (DSMEM)
    unsigned short* Lpeer    = (unsigned short*)cluster.map_shared_rank((void*)Lloc, prank);
    unsigned int*   fgw_peer = (unsigned int*)cluster.map_shared_rank((void*)fgw, prank);
    int*            misc_peer= (int*)cluster.map_shared_rank((void*)s_misc, prank);
    int*            bb_peer  = (int*)cluster.map_shared_rank((void*)s_bb, prank);
    unsigned long long* xk_peer = (unsigned long long*)cluster.map_shared_rank((void*)s_xk, prank);
    float*          xs_peer  = (float*)cluster.map_shared_rank((void*)s_xs, prank);

    // half-base table: b0 = base of half 0, b1 = base of half 1
    unsigned short* b0 = (rank == 0) ? Lloc : Lpeer;
    unsigned short* b1 = (rank == 0) ? Lpeer : Lloc;

    // ---------- Phase A: threshold, bitmap (local + mirrored to peer), labels ----------
    int fgl = 0;
    #pragma unroll 4
    for (int i = 0; i < PPT; ++i) {
        int pl = t + i * NT;                 // local pixel
        unsigned p = pixbase + pl;           // global pixel; p & 31 == lane
        float x = __ldg(&img[p]);
        float m = fmaxf((x + 1.0f) * 0.5f, 0.0f);    // exact reference arithmetic
        bool fg = m > 0.5f;
        unsigned bal = __ballot_sync(0xFFFFFFFFu, fg);
        if (lane == 0) {
            fgw[p >> 5] = bal;               // our copy
            fgw_peer[p >> 5] = bal;          // mirror to peer
        }
        if (fg) {
            unsigned zb = ~bal & (lane ? ((1u << lane) - 1u) : 0u);
            unsigned rs = zb ? (32u - (unsigned)__clz(zb)) : 0u;
            Lloc[pl] = (unsigned short)((p & ~31u) + rs);   // global run-start value
        }
        fgl += fg ? 1 : 0;
    }
    for (int o = 16; o; o >>= 1) fgl += __shfl_down_sync(0xFFFFFFFFu, fgl, o);
    if (lane == 0) s_wsi[warp] = fgl;
    if (t == 0) { s_bb[0] = HH; s_bb[1] = -1; s_bb[2] = WW; s_bb[3] = -1; }
    __syncthreads();
    if (t == 0) {
        int tot = 0;
        #pragma unroll
        for (int w = 0; w < 32; ++w) tot += s_wsi[w];
        s_misc[1] = tot;                     // LOCAL fg count
    }
    cluster.sync();                          // bitmaps + labels visible cluster-wide

    // ---------- Phase B: pruned merges (1 word per thread), R3 mask logic ----------
    {
        const int w = wordbase + t;          // global word index
        const unsigned cur = fgw[w];
        if (cur) {
            const int wc  = w & 7;
            const int row = w >> 3;
            const unsigned base = (unsigned)w << 5;

            const unsigned prev31 = (wc > 0) ? (fgw[w - 1] >> 31) & 1u : 0u;
            if ((cur & 1u) && prev31)
                merge_labels(b0, b1, base, base - 1);

            if (row > 0) {
                const unsigned up    = fgw[w - 8];
                const unsigned upl31 = (wc > 0) ? (fgw[w - 9] >> 31) & 1u : 0u;
                const unsigned upr0  = (wc < 7) ? (fgw[w - 7] & 1u) : 0u;
                const unsigned nxt0  = (wc < 7) ? (fgw[w + 1] & 1u) : 0u;

                const unsigned westc = (cur << 1) | prev31;
                const unsigned westu = (up  << 1) | upl31;
                const unsigned eastc = (cur >> 1) | (nxt0 << 31);
                const unsigned eastu = (up  >> 1) | (upr0 << 31);

                unsigned maskN  = cur & up    & ~(westc & westu);
                unsigned maskNW = cur & westu & ~up & ~westc;
                unsigned maskNE = cur & eastu & ~up & ~eastc;

                const unsigned baseu = base - WW;
                while (maskN)  { int j = __ffs(maskN)  - 1; maskN  &= maskN  - 1; merge_labels(b0, b1, base + j, baseu + j); }
                while (maskNW) { int j = __ffs(maskNW) - 1; maskNW &= maskNW - 1; merge_labels(b0, b1, base + j, baseu + j - 1); }
                while (maskNE) { int j = __ffs(maskNE) - 1; maskNE &= maskNE - 1; merge_labels(b0, b1, base + j, baseu + j + 1); }
            }
        }
    }
    cluster.sync();

    // ---------- Phase C: root-flatten local run-start entries ----------
    {
        const int w = wordbase + t;
        unsigned cur = fgw[w];
        unsigned rsm = cur & ~(cur << 1);
        const unsigned base = (unsigned)w << 5;
        while (rsm) {
            int j = __ffs(rsm) - 1; rsm &= rsm - 1;
            unsigned a = base + j;
            unsigned r = find_halve(b0, b1, a);
            Lloc[a & 0x7FFFu] = (unsigned short)r;     // a is local; write true root
        }
    }
    __syncthreads();   // local entries final (peer halving-writes are root-idempotent)

    // ---------- Phase D: per-pixel areas via Lloc[runstart] (warp-aggregated) ----------
    #pragma unroll 2
    for (int i = 0; i < PPT; ++i) {
        int pl = t + i * NT;
        unsigned p = pixbase + pl;
        unsigned word = fgw[p >> 5];                   // warp-uniform: broadcast
        bool fg = (word >> lane) & 1u;
        unsigned zb = ~word & (lane ? ((1u << lane) - 1u) : 0u);
        unsigned rs = zb ? (32u - (unsigned)__clz(zb)) : 0u;
        unsigned root = fg ? (unsigned)Lloc[(pl & ~31) + rs] : BGLAB;
        unsigned mm = __match_any_sync(0xFFFFFFFFu, root);
        if (root != BGLAB && lane == (__ffs(mm) - 1))
            atomicAdd(&area[root], __popc(mm));
    }
    __threadfence();
    cluster.sync();                          // areas complete cluster-wide

    // ---------- Phase E: local top-2 over roots, then cluster combine (+bg) ----------
    unsigned long long k1 = 0, k2 = 0;
    {
        const int w = wordbase + t;
        const unsigned cur = fgw[w];
        unsigned starts = cur & ~(cur << 1);
        const unsigned base = (unsigned)w << 5;
        while (starts) {
            int j = __ffs(starts) - 1; starts &= starts - 1;
            unsigned idx = base + j;
            if (Lloc[idx & 0x7FFFu] == (unsigned short)idx) {   // global root (owned here)
                unsigned a = (unsigned)__ldcg(&area[idx]);
                __stcg(&area[idx], 0);                           // restore zero
                unsigned long long k = ((unsigned long long)a << 17) | (0x1FFFFu - idx);
                if (k > k1) { k2 = k1; k1 = k; } else if (k > k2) k2 = k;
            }
        }
    }
    for (int o = 16; o; o >>= 1) {
        unsigned long long o1 = __shfl_down_sync(0xFFFFFFFFu, k1, o);
        unsigned long long o2 = __shfl_down_sync(0xFFFFFFFFu, k2, o);
        top2_merge(k1, k2, o1, o2);
    }
    if (lane == 0) { s_top[warp * 2] = k1; s_top[warp * 2 + 1] = k2; }
    __syncthreads();
    if (warp == 0) {
        k1 = s_top[lane * 2];
        k2 = s_top[lane * 2 + 1];
        for (int o = 16; o; o >>= 1) {
            unsigned long long o1 = __shfl_down_sync(0xFFFFFFFFu, k1, o);
            unsigned long long o2 = __shfl_down_sync(0xFFFFFFFFu, k2, o);
            top2_merge(k1, k2, o1, o2);
        }
        if (lane == 0) { s_xk[0] = k1; s_xk[1] = k2; }   // local pair
    }
    cluster.sync();
    if (t == 0) {
        unsigned long long m1 = s_xk[0], m2 = s_xk[1];
        top2_merge(m1, m2, xk_peer[0], xk_peer[1]);      // peer pair
        unsigned tot = (unsigned)s_misc[1] + (unsigned)misc_peer[1];
        unsigned bg = (unsigned)NPIX - tot;
        unsigned long long kbg = ((unsigned long long)bg << 17) | (0x1FFFFu - BGLAB);
        top2_merge(m1, m2, kbg, 0ull);
        s_misc[0] = (int)(0x1FFFFu - (unsigned)(m2 & 0x1FFFFu));   // second
    }
    __syncthreads();
    const int second = s_misc[0];

    // ---------- Phase F: per-pixel bbox of (lab == second), then cluster combine ----------
    {
        int mnr = HH, mxr = -1, mnc = WW, mxc = -1;
        #pragma unroll 2
        for (int i = 0; i < PPT; ++i) {
            int pl = t + i * NT;
            unsigned p = pixbase + pl;
            unsigned word = fgw[p >> 5];
            bool fg = (word >> lane) & 1u;
            unsigned zb = ~word & (lane ? ((1u << lane) - 1u) : 0u);
            unsigned rs = zb ? (32u - (unsigned)__clz(zb)) : 0u;
            int lab = fg ? (int)Lloc[(pl & ~31) + rs] : (int)BGLAB;
            if (lab == second) {
                int r = (int)(p >> 8), c = (int)(p & (WW - 1));
                mnr = min(mnr, r); mxr = max(mxr, r);
                mnc = min(mnc, c); mxc = max(mxc, c);
            }
        }
        if (mxr >= 0) {
            atomicMin(&s_bb[0], mnr); atomicMax(&s_bb[1], mxr);
            atomicMin(&s_bb[2], mnc); atomicMax(&s_bb[3], mxc);
        }
    }
    __syncthreads();                 // local bbox final in s_bb[0..3]
    cluster.sync();                  // peer's local bbox ready too
    if (t == 0) {
        s_bb[4] = min(s_bb[0], bb_peer[0]);
        s_bb[5] = max(s_bb[1], bb_peer[1]);
        s_bb[6] = min(s_bb[2], bb_peer[2]);
        s_bb[7] = max(s_bb[3], bb_peer[3]);
    }
    __syncthreads();
    const int h0 = s_bb[4], h1 = s_bb[5] + 1, w0 = s_bb[6], w1 = s_bb[7] + 1;
    // empty selection => inside always false => pmask == 1 (matches ref)

    // ---------- Phase G: local loss partial = sum(pmask * m) over this half ----------
    float s = 0.0f;
    #pragma unroll 4
    for (int i = 0; i < PPT; ++i) {
        int pl = t + i * NT;
        unsigned p = pixbase + pl;
        float x = __ldg(&img[p]);
        float m = fmaxf((x + 1.0f) * 0.5f, 0.0f);
        int r = (int)(p >> 8), c = (int)(p & (WW - 1));
        bool inside = (r >= h0) & (r < h1) & (c >= w0) & (c < w1);
        if (!inside) s += m;
    }
    for (int o = 16; o; o >>= 1) s += __shfl_down_sync(0xFFFFFFFFu, s, o);
    if (lane == 0) s_wsf[warp] = s;
    __syncthreads();
    if (t == 0) {
        float tot = 0.0f;
        #pragma unroll
        for (int w = 0; w < 32; ++w) tot += s_wsf[w];
        s_xs[0] = tot;                       // CTA partial
    }
    cluster.sync();                          // both partials ready

    // rank0 combines, publishes per-image loss, joins grid-wide reduction
    if (t == 0) {
        if (rank == 0) {
            g_loss[img_idx] = (s_xs[0] + xs_peer[0]) * (1.0f / (float)NPIX);
        }
    }
    __threadfence();
    __syncthreads();
    if (t == 0) {
        if (rank == 0) {
            unsigned done = atomicAdd(&g_count, 1u);
            s_misc[0] = (done == NIMG - 1) ? 1 : 0;
        } else {
            s_misc[0] = 0;
        }
    }
    __syncthreads();
    if (s_misc[0]) {
        __threadfence();
        if (t < 32) {
            float s2 = __ldcg(&g_loss[t])      + __ldcg(&g_loss[t + 32])
                     + __ldcg(&g_loss[t + 64]) + __ldcg(&g_loss[t + 96]);
            for (int o = 16; o; o >>= 1) s2 += __shfl_down_sync(0xFFFFFFFFu, s2, o);
            if (t == 0) {
                out[0] = s2 * (1.0f / (float)NIMG);
                g_count = 0;                 // net-zero for graph replay
            }
        }
    }
    cluster.sync();                          // no CTA exits while peer may touch its smem
}

extern "C" void kernel_launch(void* const* d_in, const int* in_sizes, int n_in,
                              void* d_out, int out_size) {
    const float* in = (const float*)d_in[0];
    float* out = (float*)d_out;
    (void)in_sizes; (void)n_in; (void)out_size;

    cudaFuncSetAttribute(nlccs_kernel, cudaFuncAttributeMaxDynamicSharedMemorySize, SMEM_BYTES);
    nlccs_kernel<<<NIMG * 2, NT, SMEM_BYTES>>>(in, out);
}

// round 11
// speedup vs baseline: 1.3182x; 1.3182x over previous
#include <cuda_runtime.h>
#include <cooperative_groups.h>
#include <cstdint>

namespace cg = cooperative_groups;

// NLCCSCriterion — 128 independent 256x256 masks.
// R8: 2-CTA cluster per image, but LOCAL-FIRST: B1 does each half's CCL with
// purely local smem union-find (native u16 atomics); B2 stitches only the
// 256-pixel boundary row over DSMEM; C uses read-only finds (race-free).
// Labels hold GLOBAL pixel ids (bit15 = half). Phase shapes = R3 (fastest).

#define HH 256
#define WW 256
#define NPIX (HH * WW)          // 65536
#define NIMG 128
#define NT 1024
#define HALFPIX (NPIX / 2)      // 32768 per CTA
#define PPT (HALFPIX / NT)      // 32
#define LWORDS 1024             // bitmap words owned per CTA (128 rows x 8)
#define BGLAB 0x10000u

// per-CTA smem offsets (bytes)
#define OFF_L     0             // uint16 L[32768] (this half)        : 65536
#define OFF_FGW   65536         // uint32 fgw[1024] (own half)        : 4096
#define OFF_BND   69632         // uint32 fgw_bnd[8] (peer brdr row)  : 32
#define OFF_TOP   69696         // u64 warp top2[64]                  : 512
#define OFF_WSF   70208         // float warp sums[32]                : 128
#define OFF_WSI   70336         // int warp sums[32]                  : 128
#define OFF_BB    70464         // int bbox[8]                        : 32
#define OFF_MISC  70496         // int misc[2]                        : 8
#define OFF_X     70504         // u64 xk1,xk2; float xsum            : 24
#define SMEM_BYTES 70528

__device__ int      g_area[NIMG][NPIX];   // all-zero between calls (owner rezeros)
__device__ float    g_loss[NIMG];
__device__ unsigned g_count;

// ---- local-half ops (B1/C fast path): indices masked into Lloc ----
__device__ __forceinline__ unsigned short atomMinU16(unsigned short* a, unsigned short v) {
    unsigned short old = *a;
    while (old > v) {
        unsigned short prev = atomicCAS(a, old, v);
        if (prev == old) return prev;
        old = prev;
    }
    return old;
}

// path-halving find, all chain nodes in local half (valid during B1)
__device__ __forceinline__ unsigned find_local(unsigned short* Ll, unsigned a) {
    unsigned short n;
    while ((n = Ll[a & 0x7FFFu]) != (unsigned short)a) {
        unsigned short nn = Ll[n & 0x7FFFu];
        Ll[a & 0x7FFFu] = nn;
        a = nn;
    }
    return a;
}

__device__ __forceinline__ void merge_local(unsigned short* Ll, unsigned a, unsigned b) {
    while (true) {
        a = find_local(Ll, a);
        b = find_local(Ll, b);
        if (a == b) return;
        unsigned hi = a > b ? a : b;
        unsigned lo = a + b - hi;
        unsigned short old = atomMinU16(&Ll[hi & 0x7FFFu], (unsigned short)lo);
        if (old == (unsigned short)hi) return;
        a = old;
        b = lo;
    }
}

// ---- cross-half ops (B2/C): base select on bit15, 32-bit-CAS min ----
__device__ __forceinline__ unsigned short* lp(unsigned short* b0, unsigned short* b1, unsigned p) {
    unsigned short* base = (p & 0x8000u) ? b1 : b0;
    return base + (p & 0x7FFFu);
}

__device__ __forceinline__ unsigned short atomMinU16w(unsigned short* a, unsigned short v) {
    unsigned* w = (unsigned*)((uintptr_t)a & ~(uintptr_t)3);
    int sh = ((uintptr_t)a & 2) ? 16 : 0;
    unsigned old = *w;
    while (true) {
        unsigned short cur = (unsigned short)(old >> sh);
        if (cur <= v) return cur;
        unsigned nw = (old & ~(0xFFFFu << sh)) | ((unsigned)v << sh);
        unsigned prev = atomicCAS(w, old, nw);
        if (prev == old) return cur;
        old = prev;
    }
}

// read-only find across halves (no writes => race-free vs concurrent writers)
__device__ __forceinline__ unsigned find_ro(unsigned short* b0, unsigned short* b1, unsigned a) {
    unsigned short n;
    while ((n = *lp(b0, b1, a)) != (unsigned short)a) a = n;
    return a;
}

__device__ __forceinline__ void merge_cross(unsigned short* b0, unsigned short* b1,
                                            unsigned a, unsigned b) {
    while (true) {
        a = find_ro(b0, b1, a);
        b = find_ro(b0, b1, b);
        if (a == b) return;
        unsigned hi = a > b ? a : b;
        unsigned lo = a + b - hi;
        unsigned short old = atomMinU16w(lp(b0, b1, hi), (unsigned short)lo);
        if (old == (unsigned short)hi) return;
        a = old;
        b = lo;
    }
}

__device__ __forceinline__ void top2_merge(unsigned long long& k1, unsigned long long& k2,
                                           unsigned long long o1, unsigned long long o2) {
    if (o1 > k1) { k2 = (k1 > o2) ? k1 : o2; k1 = o1; }
    else if (o1 > k2) k2 = o1;
}

__global__ __launch_bounds__(NT, 2) __cluster_dims__(2, 1, 1)
void nlccs_kernel(const float* __restrict__ in, float* __restrict__ out) {
    extern __shared__ unsigned char sraw[];
    unsigned short*      Lloc   = (unsigned short*)(sraw + OFF_L);
    unsigned int*        fgw    = (unsigned int*)(sraw + OFF_FGW);
    unsigned int*        fgbnd  = (unsigned int*)(sraw + OFF_BND);
    unsigned long long*  s_top  = (unsigned long long*)(sraw + OFF_TOP);
    float*               s_wsf  = (float*)(sraw + OFF_WSF);
    int*                 s_wsi  = (int*)(sraw + OFF_WSI);
    int*                 s_bb   = (int*)(sraw + OFF_BB);
    int*                 s_misc = (int*)(sraw + OFF_MISC);
    unsigned long long*  s_xk   = (unsigned long long*)(sraw + OFF_X);
    float*               s_xs   = (float*)(sraw + OFF_X + 16);

    cg::cluster_group cluster = cg::this_cluster();
    const unsigned rank  = cluster.block_rank();
    const unsigned prank = rank ^ 1u;
    const int t    = threadIdx.x;
    const int lane = t & 31;
    const int warp = t >> 5;
    const int img_idx = blockIdx.x >> 1;
    const unsigned pixbase = rank << 15;
    const float* img  = in + (size_t)img_idx * NPIX;
    int*         area = &g_area[img_idx][0];

    unsigned short* Lpeer    = (unsigned short*)cluster.map_shared_rank((void*)Lloc, prank);
    unsigned int*   bnd_peer = (unsigned int*)cluster.map_shared_rank((void*)fgbnd, prank);
    int*            misc_peer= (int*)cluster.map_shared_rank((void*)s_misc, prank);
    int*            bb_peer  = (int*)cluster.map_shared_rank((void*)s_bb, prank);
    unsigned long long* xk_peer = (unsigned long long*)cluster.map_shared_rank((void*)s_xk, prank);
    float*          xs_peer  = (float*)cluster.map_shared_rank((void*)s_xs, prank);

    unsigned short* b0 = (rank == 0) ? Lloc : Lpeer;   // base of half 0
    unsigned short* b1 = (rank == 0) ? Lpeer : Lloc;   // base of half 1

    // ---------- Phase A: threshold, own bitmap (+8-word boundary mirror), labels ----------
    int fgl = 0;
    #pragma unroll 4
    for (int i = 0; i < PPT; ++i) {
        int pl = t + i * NT;                 // local pixel; pl & 31 == lane
        unsigned p = pixbase + pl;
        float x = __ldg(&img[p]);
        float m = fmaxf((x + 1.0f) * 0.5f, 0.0f);    // exact reference arithmetic
        bool fg = m > 0.5f;
        unsigned bal = __ballot_sync(0xFFFFFFFFu, fg);
        int wl = pl >> 5;
        if (lane == 0) {
            fgw[wl] = bal;
            if (rank == 0 && wl >= LWORDS - 8)        // row 127 words -> peer
                bnd_peer[wl - (LWORDS - 8)] = bal;
        }
        if (fg) {
            unsigned zb = ~bal & (lane ? ((1u << lane) - 1u) : 0u);
            unsigned rs = zb ? (32u - (unsigned)__clz(zb)) : 0u;
            Lloc[pl] = (unsigned short)((p & ~31u) + rs);   // GLOBAL run-start value
        }
        fgl += fg ? 1 : 0;
    }
    for (int o = 16; o; o >>= 1) fgl += __shfl_down_sync(0xFFFFFFFFu, fgl, o);
    if (lane == 0) s_wsi[warp] = fgl;
    if (t == 0) { s_bb[0] = HH; s_bb[1] = -1; s_bb[2] = WW; s_bb[3] = -1; }
    __syncthreads();
    if (t == 0) {
        int tot = 0;
        #pragma unroll
        for (int w = 0; w < 32; ++w) tot += s_wsi[w];
        s_misc[1] = tot;                     // local fg count
    }
    cluster.sync();                          // labels + boundary bitmap visible

    // ---------- Phase B1: local-half pruned merges (1 word/thread, all LOCAL) ----------
    {
        const int wl = t;                    // local word 0..1023
        const unsigned cur = fgw[wl];
        if (cur) {
            const int wc   = wl & 7;
            const int rloc = wl >> 3;        // local row
            const unsigned base = pixbase + ((unsigned)wl << 5);

            const unsigned prev31 = (wc > 0) ? (fgw[wl - 1] >> 31) & 1u : 0u;
            if ((cur & 1u) && prev31)
                merge_local(Lloc, base, base - 1);

            if (rloc > 0) {                  // vertical merges stay inside this half
                const unsigned up    = fgw[wl - 8];
                const unsigned upl31 = (wc > 0) ? (fgw[wl - 9] >> 31) & 1u : 0u;
                const unsigned upr0  = (wc < 7) ? (fgw[wl - 7] & 1u) : 0u;
                const unsigned nxt0  = (wc < 7) ? (fgw[wl + 1] & 1u) : 0u;

                const unsigned westc = (cur << 1) | prev31;
                const unsigned westu = (up  << 1) | upl31;
                const unsigned eastc = (cur >> 1) | (nxt0 << 31);
                const unsigned eastu = (up  >> 1) | (upr0 << 31);

                unsigned maskN  = cur & up    & ~(westc & westu);
                unsigned maskNW = cur & westu & ~up & ~westc;
                unsigned maskNE = cur & eastu & ~up & ~eastc;

                const unsigned baseu = base - WW;
                while (maskN)  { int j = __ffs(maskN)  - 1; maskN  &= maskN  - 1; merge_local(Lloc, base + j, baseu + j); }
                while (maskNW) { int j = __ffs(maskNW) - 1; maskNW &= maskNW - 1; merge_local(Lloc, base + j, baseu + j - 1); }
                while (maskNE) { int j = __ffs(maskNE) - 1; maskNE &= maskNE - 1; merge_local(Lloc, base + j, baseu + j + 1); }
            }
        }
    }
    cluster.sync();                          // both halves' local CCL done

    // ---------- Phase B2: boundary stitch (CTA1, lane-per-bit over 8 words) ----------
    if (rank == 1 && t < 256) {
        const int wc = t >> 5;               // word in row 128
        const int j  = t & 31;               // bit
        const unsigned cur = fgw[wc];
        const unsigned up  = fgbnd[wc];      // peer row 127
        if (cur | up) {
            const unsigned prev31 = (wc > 0) ? (fgw[wc - 1] >> 31) & 1u : 0u;
            const unsigned upl31  = (wc > 0) ? (fgbnd[wc - 1] >> 31) & 1u : 0u;
            const unsigned upr0   = (wc < 7) ? (fgbnd[wc + 1] & 1u) : 0u;
            const unsigned nxt0   = (wc < 7) ? (fgw[wc + 1] & 1u) : 0u;

            const unsigned westc = (cur << 1) | prev31;
            const unsigned westu = (up  << 1) | upl31;
            const unsigned eastc = (cur >> 1) | (nxt0 << 31);
            const unsigned eastu = (up  >> 1) | (upr0 << 31);

            const unsigned maskN  = cur & up    & ~(westc & westu);
            const unsigned maskNW = cur & westu & ~up & ~westc;
            const unsigned maskNE = cur & eastu & ~up & ~eastc;

            const unsigned base  = (1u << 15) + ((unsigned)wc << 5);   // row 128
            const unsigned baseu = base - WW;                          // row 127 (half 0)
            const unsigned bit = 1u << j;
            if (maskN  & bit) merge_cross(b0, b1, base + j, baseu + j);
            if (maskNW & bit) merge_cross(b0, b1, base + j, baseu + j - 1);
            if (maskNE & bit) merge_cross(b0, b1, base + j, baseu + j + 1);
        }
    }
    cluster.sync();                          // all merges done cluster-wide

    // ---------- Phase C: read-only root-flatten of own run-start entries ----------
    {
        const int wl = t;
        unsigned cur = fgw[wl];
        unsigned rsm = cur & ~(cur << 1);
        const unsigned base = pixbase + ((unsigned)wl << 5);
        while (rsm) {
            int j = __ffs(rsm) - 1; rsm &= rsm - 1;
            unsigned a = base + j;
            unsigned r = find_ro(b0, b1, a);          // no writes: race-free
            Lloc[(a & 0x7FFFu)] = (unsigned short)r;  // own entry := true root
        }
    }
    __syncthreads();                         // own entries final; peer never writes them

    // ---------- Phase D: per-pixel areas via Lloc[runstart] (warp-aggregated) ----------
    #pragma unroll 2
    for (int i = 0; i < PPT; ++i) {
        int pl = t + i * NT;
        unsigned word = fgw[pl >> 5];                 // warp-uniform: broadcast
        bool fg = (word >> lane) & 1u;
        unsigned zb = ~word & (lane ? ((1u << lane) - 1u) : 0u);
        unsigned rs = zb ? (32u - (unsigned)__clz(zb)) : 0u;
        unsigned root = fg ? (unsigned)Lloc[(pl & ~31) + rs] : BGLAB;
        unsigned mm = __match_any_sync(0xFFFFFFFFu, root);
        if (root != BGLAB && lane == (__ffs(mm) - 1))
            atomicAdd(&area[root], __popc(mm));
    }
    __threadfence();
    cluster.sync();                          // both halves' areas complete

    // ---------- Phase E: local top-2 over owned roots, then cluster combine (+bg) ----------
    unsigned long long k1 = 0, k2 = 0;
    {
        const int wl = t;
        const unsigned cur = fgw[wl];
        unsigned starts = cur & ~(cur << 1);
        const unsigned base = pixbase + ((unsigned)wl << 5);
        while (starts) {
            int j = __ffs(starts) - 1; starts &= starts - 1;
            unsigned idx = base + j;
            if (Lloc[idx & 0x7FFFu] == (unsigned short)idx) {   // root owned here
                unsigned a = (unsigned)__ldcg(&area[idx]);
                __stcg(&area[idx], 0);                           // restore zero
                unsigned long long k = ((unsigned long long)a << 17) | (0x1FFFFu - idx);
                if (k > k1) { k2 = k1; k1 = k; } else if (k > k2) k2 = k;
            }
        }
    }
    for (int o = 16; o; o >>= 1) {
        unsigned long long o1 = __shfl_down_sync(0xFFFFFFFFu, k1, o);
        unsigned long long o2 = __shfl_down_sync(0xFFFFFFFFu, k2, o);
        top2_merge(k1, k2, o1, o2);
    }
    if (lane == 0) { s_top[warp * 2] = k1; s_top[warp * 2 + 1] = k2; }
    __syncthreads();
    if (warp == 0) {
        k1 = s_top[lane * 2];
        k2 = s_top[lane * 2 + 1];
        for (int o = 16; o; o >>= 1) {
            unsigned long long o1 = __shfl_down_sync(0xFFFFFFFFu, k1, o);
            unsigned long long o2 = __shfl_down_sync(0xFFFFFFFFu, k2, o);
            top2_merge(k1, k2, o1, o2);
        }
        if (lane == 0) { s_xk[0] = k1; s_xk[1] = k2; }
    }
    cluster.sync();
    if (t == 0) {
        unsigned long long m1 = s_xk[0], m2 = s_xk[1];
        top2_merge(m1, m2, xk_peer[0], xk_peer[1]);
        unsigned tot = (unsigned)s_misc[1] + (unsigned)misc_peer[1];
        unsigned bg = (unsigned)NPIX - tot;
        unsigned long long kbg = ((unsigned long long)bg << 17) | (0x1FFFFu - BGLAB);
        top2_merge(m1, m2, kbg, 0ull);
        s_misc[0] = (int)(0x1FFFFu - (unsigned)(m2 & 0x1FFFFu));   // second
    }
    __syncthreads();
    const int second = s_misc[0];

    // ---------- Phase F: per-pixel bbox of (lab == second), cluster combine ----------
    {
        int mnr = HH, mxr = -1, mnc = WW, mxc = -1;
        #pragma unroll 2
        for (int i = 0; i < PPT; ++i) {
            int pl = t + i * NT;
            unsigned p = pixbase + pl;
            unsigned word = fgw[pl >> 5];
            bool fg = (word >> lane) & 1u;
            unsigned zb = ~word & (lane ? ((1u << lane) - 1u) : 0u);
            unsigned rs = zb ? (32u - (unsigned)__clz(zb)) : 0u;
            int lab = fg ? (int)Lloc[(pl & ~31) + rs] : (int)BGLAB;
            if (lab == second) {
                int r = (int)(p >> 8), c = (int)(p & (WW - 1));
                mnr = min(mnr, r); mxr = max(mxr, r);
                mnc = min(mnc, c); mxc = max(mxc, c);
            }
        }
        if (mxr >= 0) {
            atomicMin(&s_bb[0], mnr); atomicMax(&s_bb[1], mxr);
            atomicMin(&s_bb[2], mnc); atomicMax(&s_bb[3], mxc);
        }
    }
    __syncthreads();
    cluster.sync();
    if (t == 0) {
        s_bb[4] = min(s_bb[0], bb_peer[0]);
        s_bb[5] = max(s_bb[1], bb_peer[1]);
        s_bb[6] = min(s_bb[2], bb_peer[2]);
        s_bb[7] = max(s_bb[3], bb_peer[3]);
    }
    __syncthreads();
    const int h0 = s_bb[4], h1 = s_bb[5] + 1, w0 = s_bb[6], w1 = s_bb[7] + 1;
    // empty selection => inside always false => pmask == 1 (matches ref)

    // ---------- Phase G: local partial of sum(pmask * m) ----------
    float s = 0.0f;
    #pragma unroll 4
    for (int i = 0; i < PPT; ++i) {
        int pl = t + i * NT;
        unsigned p = pixbase + pl;
        float x = __ldg(&img[p]);
        float m = fmaxf((x + 1.0f) * 0.5f, 0.0f);
        int r = (int)(p >> 8), c = (int)(p & (WW - 1));
        bool inside = (r >= h0) & (r < h1) & (c >= w0) & (c < w1);
        if (!inside) s += m;
    }
    for (int o = 16; o; o >>= 1) s += __shfl_down_sync(0xFFFFFFFFu, s, o);
    if (lane == 0) s_wsf[warp] = s;
    __syncthreads();
    if (t == 0) {
        float tot = 0.0f;
        #pragma unroll
        for (int w = 0; w < 32; ++w) tot += s_wsf[w];
        s_xs[0] = tot;
    }
    cluster.sync();

    if (t == 0 && rank == 0)
        g_loss[img_idx] = (s_xs[0] + xs_peer[0]) * (1.0f / (float)NPIX);
    __threadfence();
    __syncthreads();
    if (t == 0) {
        if (rank == 0) {
            unsigned done = atomicAdd(&g_count, 1u);
            s_misc[0] = (done == NIMG - 1) ? 1 : 0;
        } else {
            s_misc[0] = 0;
        }
    }
    __syncthreads();
    if (s_misc[0]) {
        __threadfence();
        if (t < 32) {
            float s2 = __ldcg(&g_loss[t])      + __ldcg(&g_loss[t + 32])
                     + __ldcg(&g_loss[t + 64]) + __ldcg(&g_loss[t + 96]);
            for (int o = 16; o; o >>= 1) s2 += __shfl_down_sync(0xFFFFFFFFu, s2, o);
            if (t == 0) {
                out[0] = s2 * (1.0f / (float)NIMG);
                g_count = 0;
            }
        }
    }
    cluster.sync();                          // peer may still read our smem above
}

extern "C" void kernel_launch(void* const* d_in, const int* in_sizes, int n_in,
                              void* d_out, int out_size) {
    const float* in = (const float*)d_in[0];
    float* out = (float*)d_out;
    (void)in_sizes; (void)n_in; (void)out_size;

    cudaFuncSetAttribute(nlccs_kernel, cudaFuncAttributeMaxDynamicSharedMemorySize, SMEM_BYTES);
    nlccs_kernel<<<NIMG * 2, NT, SMEM_BYTES>>>(in, out);
}

// round 13
// speedup vs baseline: 1.3444x; 1.0199x over previous
#include <cuda_runtime.h>
#include <cooperative_groups.h>
#include <cstdint>

namespace cg = cooperative_groups;

// NLCCSCriterion — 128 independent 256x256 masks.
// R9 (re-bench after infra failure) = R8 base (2-CTA cluster, local-first CCL,
// boundary stitch) with:
//  - region-based Phase G (iterate only outside-bbox pixels)
//  - fg count moved from Phase A to a popc in B1
//  - boundary bitmap mirror hoisted out of the A loop

#define HH 256
#define WW 256
#define NPIX (HH * WW)          // 65536
#define NIMG 128
#define NT 1024
#define HALFPIX (NPIX / 2)      // 32768 per CTA
#define PPT (HALFPIX / NT)      // 32
#define LWORDS 1024             // bitmap words owned per CTA (128 rows x 8)
#define BGLAB 0x10000u

// per-CTA smem offsets (bytes)
#define OFF_L     0             // uint16 L[32768] (this half)        : 65536
#define OFF_FGW   65536         // uint32 fgw[1024] (own half)        : 4096
#define OFF_BND   69632         // uint32 fgw_bnd[8] (peer brdr row)  : 32
#define OFF_TOP   69696         // u64 warp top2[64]                  : 512
#define OFF_WSF   70208         // float warp sums[32]                : 128
#define OFF_WSI   70336         // int warp sums[32]                  : 128
#define OFF_BB    70464         // int bbox[8]                        : 32
#define OFF_MISC  70496         // int misc[2]                        : 8
#define OFF_X     70504         // u64 xk1,xk2; float xsum            : 24
#define SMEM_BYTES 70528

__device__ int      g_area[NIMG][NPIX];   // all-zero between calls (owner rezeros)
__device__ float    g_loss[NIMG];
__device__ unsigned g_count;

// ---- local-half ops (B1/C fast path) ----
__device__ __forceinline__ unsigned short atomMinU16(unsigned short* a, unsigned short v) {
    unsigned short old = *a;
    while (old > v) {
        unsigned short prev = atomicCAS(a, old, v);
        if (prev == old) return prev;
        old = prev;
    }
    return old;
}

__device__ __forceinline__ unsigned find_local(unsigned short* Ll, unsigned a) {
    unsigned short n;
    while ((n = Ll[a & 0x7FFFu]) != (unsigned short)a) {
        unsigned short nn = Ll[n & 0x7FFFu];
        Ll[a & 0x7FFFu] = nn;
        a = nn;
    }
    return a;
}

__device__ __forceinline__ void merge_local(unsigned short* Ll, unsigned a, unsigned b) {
    while (true) {
        a = find_local(Ll, a);
        b = find_local(Ll, b);
        if (a == b) return;
        unsigned hi = a > b ? a : b;
        unsigned lo = a + b - hi;
        unsigned short old = atomMinU16(&Ll[hi & 0x7FFFu], (unsigned short)lo);
        if (old == (unsigned short)hi) return;
        a = old;
        b = lo;
    }
}

// ---- cross-half ops (B2/C) ----
__device__ __forceinline__ unsigned short* lp(unsigned short* b0, unsigned short* b1, unsigned p) {
    unsigned short* base = (p & 0x8000u) ? b1 : b0;
    return base + (p & 0x7FFFu);
}

__device__ __forceinline__ unsigned short atomMinU16w(unsigned short* a, unsigned short v) {
    unsigned* w = (unsigned*)((uintptr_t)a & ~(uintptr_t)3);
    int sh = ((uintptr_t)a & 2) ? 16 : 0;
    unsigned old = *w;
    while (true) {
        unsigned short cur = (unsigned short)(old >> sh);
        if (cur <= v) return cur;
        unsigned nw = (old & ~(0xFFFFu << sh)) | ((unsigned)v << sh);
        unsigned prev = atomicCAS(w, old, nw);
        if (prev == old) return cur;
        old = prev;
    }
}

__device__ __forceinline__ unsigned find_ro(unsigned short* b0, unsigned short* b1, unsigned a) {
    unsigned short n;
    while ((n = *lp(b0, b1, a)) != (unsigned short)a) a = n;
    return a;
}

__device__ __forceinline__ void merge_cross(unsigned short* b0, unsigned short* b1,
                                            unsigned a, unsigned b) {
    while (true) {
        a = find_ro(b0, b1, a);
        b = find_ro(b0, b1, b);
        if (a == b) return;
        unsigned hi = a > b ? a : b;
        unsigned lo = a + b - hi;
        unsigned short old = atomMinU16w(lp(b0, b1, hi), (unsigned short)lo);
        if (old == (unsigned short)hi) return;
        a = old;
        b = lo;
    }
}

__device__ __forceinline__ void top2_merge(unsigned long long& k1, unsigned long long& k2,
                                           unsigned long long o1, unsigned long long o2) {
    if (o1 > k1) { k2 = (k1 > o2) ? k1 : o2; k1 = o1; }
    else if (o1 > k2) k2 = o1;
}

__global__ __launch_bounds__(NT, 2) __cluster_dims__(2, 1, 1)
void nlccs_kernel(const float* __restrict__ in, float* __restrict__ out) {
    extern __shared__ unsigned char sraw[];
    unsigned short*      Lloc   = (unsigned short*)(sraw + OFF_L);
    unsigned int*        fgw    = (unsigned int*)(sraw + OFF_FGW);
    unsigned int*        fgbnd  = (unsigned int*)(sraw + OFF_BND);
    unsigned long long*  s_top  = (unsigned long long*)(sraw + OFF_TOP);
    float*               s_wsf  = (float*)(sraw + OFF_WSF);
    int*                 s_wsi  = (int*)(sraw + OFF_WSI);
    int*                 s_bb   = (int*)(sraw + OFF_BB);
    int*                 s_misc = (int*)(sraw + OFF_MISC);
    unsigned long long*  s_xk   = (unsigned long long*)(sraw + OFF_X);
    float*               s_xs   = (float*)(sraw + OFF_X + 16);

    cg::cluster_group cluster = cg::this_cluster();
    const unsigned rank  = cluster.block_rank();
    const unsigned prank = rank ^ 1u;
    const int t    = threadIdx.x;
    const int lane = t & 31;
    const int warp = t >> 5;
    const int img_idx = blockIdx.x >> 1;
    const unsigned pixbase = rank << 15;
    const float* img  = in + (size_t)img_idx * NPIX;
    int*         area = &g_area[img_idx][0];

    unsigned short* Lpeer    = (unsigned short*)cluster.map_shared_rank((void*)Lloc, prank);
    unsigned int*   bnd_peer = (unsigned int*)cluster.map_shared_rank((void*)fgbnd, prank);
    int*            misc_peer= (int*)cluster.map_shared_rank((void*)s_misc, prank);
    int*            bb_peer  = (int*)cluster.map_shared_rank((void*)s_bb, prank);
    unsigned long long* xk_peer = (unsigned long long*)cluster.map_shared_rank((void*)s_xk, prank);
    float*          xs_peer  = (float*)cluster.map_shared_rank((void*)s_xs, prank);

    unsigned short* b0 = (rank == 0) ? Lloc : Lpeer;   // base of half 0
    unsigned short* b1 = (rank == 0) ? Lpeer : Lloc;   // base of half 1

    // ---------- Phase A: threshold, own bitmap, run-start labels ----------
    #pragma unroll 4
    for (int i = 0; i < PPT; ++i) {
        int pl = t + i * NT;                 // local pixel; pl & 31 == lane
        unsigned p = pixbase + pl;
        float x = __ldg(&img[p]);
        float m = fmaxf((x + 1.0f) * 0.5f, 0.0f);    // exact reference arithmetic
        bool fg = m > 0.5f;
        unsigned bal = __ballot_sync(0xFFFFFFFFu, fg);
        if (lane == 0) fgw[pl >> 5] = bal;
        if (fg) {
            unsigned zb = ~bal & (lane ? ((1u << lane) - 1u) : 0u);
            unsigned rs = zb ? (32u - (unsigned)__clz(zb)) : 0u;
            Lloc[pl] = (unsigned short)((p & ~31u) + rs);   // GLOBAL run-start value
        }
    }
    if (t == 0) { s_bb[0] = HH; s_bb[1] = -1; s_bb[2] = WW; s_bb[3] = -1; }
    __syncthreads();
    if (rank == 0 && t < 8) bnd_peer[t] = fgw[LWORDS - 8 + t];   // row 127 -> peer
    cluster.sync();                          // labels + boundary bitmap visible

    // ---------- Phase B1: local-half pruned merges (1 word/thread) + fg popc ----------
    {
        const int wl = t;                    // local word 0..1023
        const unsigned cur = fgw[wl];
        int myfg = __popc(cur);
        for (int o = 16; o; o >>= 1) myfg += __shfl_down_sync(0xFFFFFFFFu, myfg, o);
        if (lane == 0) s_wsi[warp] = myfg;
        if (cur) {
            const int wc   = wl & 7;
            const int rloc = wl >> 3;        // local row
            const unsigned base = pixbase + ((unsigned)wl << 5);

            const unsigned prev31 = (wc > 0) ? (fgw[wl - 1] >> 31) & 1u : 0u;
            if ((cur & 1u) && prev31)
                merge_local(Lloc, base, base - 1);

            if (rloc > 0) {                  // vertical merges stay inside this half
                const unsigned up    = fgw[wl - 8];
                const unsigned upl31 = (wc > 0) ? (fgw[wl - 9] >> 31) & 1u : 0u;
                const unsigned upr0  = (wc < 7) ? (fgw[wl - 7] & 1u) : 0u;
                const unsigned nxt0  = (wc < 7) ? (fgw[wl + 1] & 1u) : 0u;

                const unsigned westc = (cur << 1) | prev31;
                const unsigned westu = (up  << 1) | upl31;
                const unsigned eastc = (cur >> 1) | (nxt0 << 31);
                const unsigned eastu = (up  >> 1) | (upr0 << 31);

                unsigned maskN  = cur & up    & ~(westc & westu);
                unsigned maskNW = cur & westu & ~up & ~westc;
                unsigned maskNE = cur & eastu & ~up & ~eastc;

                const unsigned baseu = base - WW;
                while (maskN)  { int j = __ffs(maskN)  - 1; maskN  &= maskN  - 1; merge_local(Lloc, base + j, baseu + j); }
                while (maskNW) { int j = __ffs(maskNW) - 1; maskNW &= maskNW - 1; merge_local(Lloc, base + j, baseu + j - 1); }
                while (maskNE) { int j = __ffs(maskNE) - 1; maskNE &= maskNE - 1; merge_local(Lloc, base + j, baseu + j + 1); }
            }
        }
    }
    cluster.sync();                          // both halves' local CCL done
    if (t == 0) {                            // local fg total (read at E-combine, later syncs order it)
        int tot = 0;
        #pragma unroll
        for (int w = 0; w < 32; ++w) tot += s_wsi[w];
        s_misc[1] = tot;
    }

    // ---------- Phase B2: boundary stitch (CTA1, lane-per-bit over 8 words) ----------
    if (rank == 1 && t < 256) {
        const int wc = t >> 5;               // word in row 128
        const int j  = t & 31;               // bit
        const unsigned cur = fgw[wc];
        const unsigned up  = fgbnd[wc];      // peer row 127
        if (cur | up) {
            const unsigned prev31 = (wc > 0) ? (fgw[wc - 1] >> 31) & 1u : 0u;
            const unsigned upl31  = (wc > 0) ? (fgbnd[wc - 1] >> 31) & 1u : 0u;
            const unsigned upr0   = (wc < 7) ? (fgbnd[wc + 1] & 1u) : 0u;
            const unsigned nxt0   = (wc < 7) ? (fgw[wc + 1] & 1u) : 0u;

            const unsigned westc = (cur << 1) | prev31;
            const unsigned westu = (up  << 1) | upl31;
            const unsigned eastc = (cur >> 1) | (nxt0 << 31);
            const unsigned eastu = (up  >> 1) | (upr0 << 31);

            const unsigned maskN  = cur & up    & ~(westc & westu);
            const unsigned maskNW = cur & westu & ~up & ~westc;
            const unsigned maskNE = cur & eastu & ~up & ~eastc;

            const unsigned base  = (1u << 15) + ((unsigned)wc << 5);   // row 128
            const unsigned baseu = base - WW;                          // row 127 (half 0)
            const unsigned bit = 1u << j;
            if (maskN  & bit) merge_cross(b0, b1, base + j, baseu + j);
            if (maskNW & bit) merge_cross(b0, b1, base + j, baseu + j - 1);
            if (maskNE & bit) merge_cross(b0, b1, base + j, baseu + j + 1);
        }
    }
    cluster.sync();                          // all merges done cluster-wide

    // ---------- Phase C: read-only root-flatten of own run-start entries ----------
    {
        const int wl = t;
        unsigned cur = fgw[wl];
        unsigned rsm = cur & ~(cur << 1);
        const unsigned base = pixbase + ((unsigned)wl << 5);
        while (rsm) {
            int j = __ffs(rsm) - 1; rsm &= rsm - 1;
            unsigned a = base + j;
            unsigned r = find_ro(b0, b1, a);          // no writes: race-free
            Lloc[(a & 0x7FFFu)] = (unsigned short)r;  // own entry := true root
        }
    }
    __syncthreads();                         // own entries final; peer never writes them

    // ---------- Phase D: per-pixel areas via Lloc[runstart] (warp-aggregated) ----------
    #pragma unroll 2
    for (int i = 0; i < PPT; ++i) {
        int pl = t + i * NT;
        unsigned word = fgw[pl >> 5];                 // warp-uniform: broadcast
        bool fg = (word >> lane) & 1u;
        unsigned zb = ~word & (lane ? ((1u << lane) - 1u) : 0u);
        unsigned rs = zb ? (32u - (unsigned)__clz(zb)) : 0u;
        unsigned root = fg ? (unsigned)Lloc[(pl & ~31) + rs] : BGLAB;
        unsigned mm = __match_any_sync(0xFFFFFFFFu, root);
        if (root != BGLAB && lane == (__ffs(mm) - 1))
            atomicAdd(&area[root], __popc(mm));
    }
    __threadfence();
    cluster.sync();                          // both halves' areas complete

    // ---------- Phase E: local top-2 over owned roots, then cluster combine (+bg) ----------
    unsigned long long k1 = 0, k2 = 0;
    {
        const int wl = t;
        const unsigned cur = fgw[wl];
        unsigned starts = cur & ~(cur << 1);
        const unsigned base = pixbase + ((unsigned)wl << 5);
        while (starts) {
            int j = __ffs(starts) - 1; starts &= starts - 1;
            unsigned idx = base + j;
            if (Lloc[idx & 0x7FFFu] == (unsigned short)idx) {   // root owned here
                unsigned a = (unsigned)__ldcg(&area[idx]);
                __stcg(&area[idx], 0);                           // restore zero
                unsigned long long k = ((unsigned long long)a << 17) | (0x1FFFFu - idx);
                if (k > k1) { k2 = k1; k1 = k; } else if (k > k2) k2 = k;
            }
        }
    }
    for (int o = 16; o; o >>= 1) {
        unsigned long long o1 = __shfl_down_sync(0xFFFFFFFFu, k1, o);
        unsigned long long o2 = __shfl_down_sync(0xFFFFFFFFu, k2, o);
        top2_merge(k1, k2, o1, o2);
    }
    if (lane == 0) { s_top[warp * 2] = k1; s_top[warp * 2 + 1] = k2; }
    __syncthreads();
    if (warp == 0) {
        k1 = s_top[lane * 2];
        k2 = s_top[lane * 2 + 1];
        for (int o = 16; o; o >>= 1) {
            unsigned long long o1 = __shfl_down_sync(0xFFFFFFFFu, k1, o);
            unsigned long long o2 = __shfl_down_sync(0xFFFFFFFFu, k2, o);
            top2_merge(k1, k2, o1, o2);
        }
        if (lane == 0) { s_xk[0] = k1; s_xk[1] = k2; }
    }
    cluster.sync();
    if (t == 0) {
        unsigned long long m1 = s_xk[0], m2 = s_xk[1];
        top2_merge(m1, m2, xk_peer[0], xk_peer[1]);
        unsigned tot = (unsigned)s_misc[1] + (unsigned)misc_peer[1];
        unsigned bg = (unsigned)NPIX - tot;
        unsigned long long kbg = ((unsigned long long)bg << 17) | (0x1FFFFu - BGLAB);
        top2_merge(m1, m2, kbg, 0ull);
        s_misc[0] = (int)(0x1FFFFu - (unsigned)(m2 & 0x1FFFFu));   // second
    }
    __syncthreads();
    const int second = s_misc[0];

    // ---------- Phase F: per-pixel bbox of (lab == second), cluster combine ----------
    {
        int mnr = HH, mxr = -1, mnc = WW, mxc = -1;
        #pragma unroll 2
        for (int i = 0; i < PPT; ++i) {
            int pl = t + i * NT;
            unsigned p = pixbase + pl;
            unsigned word = fgw[pl >> 5];
            bool fg = (word >> lane) & 1u;
            unsigned zb = ~word & (lane ? ((1u << lane) - 1u) : 0u);
            unsigned rs = zb ? (32u - (unsigned)__clz(zb)) : 0u;
            int lab = fg ? (int)Lloc[(pl & ~31) + rs] : (int)BGLAB;
            if (lab == second) {
                int r = (int)(p >> 8), c = (int)(p & (WW - 1));
                mnr = min(mnr, r); mxr = max(mxr, r);
                mnc = min(mnc, c); mxc = max(mxc, c);
            }
        }
        if (mxr >= 0) {
            atomicMin(&s_bb[0], mnr); atomicMax(&s_bb[1], mxr);
            atomicMin(&s_bb[2], mnc); atomicMax(&s_bb[3], mxc);
        }
    }
    __syncthreads();
    cluster.sync();
    if (t == 0) {
        s_bb[4] = min(s_bb[0], bb_peer[0]);
        s_bb[5] = max(s_bb[1], bb_peer[1]);
        s_bb[6] = min(s_bb[2], bb_peer[2]);
        s_bb[7] = max(s_bb[3], bb_peer[3]);
    }
    __syncthreads();
    const int h0 = s_bb[4], h1 = s_bb[5] + 1, w0 = s_bb[6], w1 = s_bb[7] + 1;
    // empty selection => h0=256,h1=0 => every row "outside" => pmask == 1 (matches ref)

    // ---------- Phase G: REGION-BASED sum of outside-bbox m (own half only) ----------
    float s = 0.0f;
    {
        const int myr0 = (int)(rank << 7);
        const int myr1 = myr0 + 128;
        for (int r = myr0 + warp; r < myr1; r += 32) {       // warp-per-row
            const float* rowp = img + (r << 8);
            if ((r < h0) | (r >= h1)) {                      // whole row outside
                for (int c = lane; c < WW; c += 32) {
                    float x = __ldg(&rowp[c]);
                    s += fmaxf((x + 1.0f) * 0.5f, 0.0f);
                }
            } else {                                          // only side strips outside
                for (int c = lane; c < w0; c += 32) {
                    float x = __ldg(&rowp[c]);
                    s += fmaxf((x + 1.0f) * 0.5f, 0.0f);
                }
                for (int c = w1 + lane; c < WW; c += 32) {
                    float x = __ldg(&rowp[c]);
                    s += fmaxf((x + 1.0f) * 0.5f, 0.0f);
                }
            }
        }
    }
    for (int o = 16; o; o >>= 1) s += __shfl_down_sync(0xFFFFFFFFu, s, o);
    if (lane == 0) s_wsf[warp] = s;
    __syncthreads();
    if (t == 0) {
        float tot = 0.0f;
        #pragma unroll
        for (int w = 0; w < 32; ++w) tot += s_wsf[w];
        s_xs[0] = tot;
    }
    cluster.sync();

    if (t == 0 && rank == 0)
        g_loss[img_idx] = (s_xs[0] + xs_peer[0]) * (1.0f / (float)NPIX);
    __threadfence();
    __syncthreads();
    if (t == 0) {
        if (rank == 0) {
            unsigned done = atomicAdd(&g_count, 1u);
            s_misc[0] = (done == NIMG - 1) ? 1 : 0;
        } else {
            s_misc[0] = 0;
        }
    }
    __syncthreads();
    if (s_misc[0]) {
        __threadfence();
        if (t < 32) {
            float s2 = __ldcg(&g_loss[t])      + __ldcg(&g_loss[t + 32])
                     + __ldcg(&g_loss[t + 64]) + __ldcg(&g_loss[t + 96]);
            for (int o = 16; o; o >>= 1) s2 += __shfl_down_sync(0xFFFFFFFFu, s2, o);
            if (t == 0) {
                out[0] = s2 * (1.0f / (float)NIMG);
                g_count = 0;
            }
        }
    }
    cluster.sync();                          // peer may still read our smem above
}

extern "C" void kernel_launch(void* const* d_in, const int* in_sizes, int n_in,
                              void* d_out, int out_size) {
    const float* in = (const float*)d_in[0];
    float* out = (float*)d_out;
    (void)in_sizes; (void)n_in; (void)out_size;

    cudaFuncSetAttribute(nlccs_kernel, cudaFuncAttributeMaxDynamicSharedMemorySize, SMEM_BYTES);
    nlccs_kernel<<<NIMG * 2, NT, SMEM_BYTES>>>(in, out);
}